// round 5
// baseline (speedup 1.0000x reference)
#include <cuda_runtime.h>
#include <math.h>

// ---------------- problem constants ----------------
#define BB 4
#define HH 256
#define WW 256
#define CC 32
#define NPIX (HH*WW)            // 65536
#define IMG_ELEMS (BB*NPIX*CC)  // 8388608

typedef unsigned long long ull;

// ---------------- device scratch ----------------
__device__ float g_part[BB*256*1056];
__device__ float g_M[BB*1024];
__device__ float g_cmask[BB*CC];
__device__ float g_smask[BB*NPIX];
__device__ float g_kcomb[49*32];
__device__ float g_vg[IMG_ELEMS];
__device__ float g_vspec[IMG_ELEMS];
__device__ float g_tpos[IMG_ELEMS];
__device__ float g_outn[IMG_ELEMS];

__device__ __forceinline__ float gelu_exact(float x) {
    return 0.5f * x * (1.0f + erff(x * 0.70710678118654752f));
}
__device__ __forceinline__ float sigmoidf_(float x) {
    return 1.0f / (1.0f + expf(-x));
}

// ---------------- packed f32x2 helpers ----------------
__device__ __forceinline__ void fma2(ull& c, ull a, ull b) {
    asm("fma.rn.f32x2 %0, %1, %2, %0;" : "+l"(c) : "l"(a), "l"(b));
}
__device__ __forceinline__ ull pk2(float x) {          // {x, x}
    ull r; asm("mov.b64 %0, {%1, %1};" : "=l"(r) : "f"(x)); return r;
}
__device__ __forceinline__ float2 upk(ull v) {
    float2 f; asm("mov.b64 {%0, %1}, %2;" : "=f"(f.x), "=f"(f.y) : "l"(v)); return f;
}
__device__ __forceinline__ float hadd2(ull v) {
    float2 f = upk(v); return f.x + f.y;
}

// ---------------- 0) fold spatial-attention kernels ----------------
__global__ void prep_k(const float* __restrict__ c1a, const float* __restrict__ c1b,
                       const float* __restrict__ c2a, const float* __restrict__ c2b,
                       const float* __restrict__ c3) {
    int tid = threadIdx.x;
    float w3 = c3[0], w7 = c3[1];
    for (int e = tid; e < 49*32; e += 256) {
        int t = e >> 5, i = e & 31;
        int ty = t / 7 - 3, tx = t % 7 - 3;
        float s = 0.f;
        for (int o = 0; o < 32; o++)
            s += c2b[o] * c2a[((o*32 + i)*7 + (tx+3))*7 + (ty+3)];
        s *= w7;
        if (tx >= -1 && tx <= 1 && ty >= -1 && ty <= 1) {
            float s1 = 0.f;
            for (int o = 0; o < 32; o++)
                s1 += c1b[o] * c1a[((o*32 + i)*3 + (tx+1))*3 + (ty+1)];
            s += w3 * s1;
        }
        g_kcomb[e] = s;
    }
}

// ---------------- 1) stats stage 1 ----------------
__global__ __launch_bounds__(256) void stats1_k(const float* __restrict__ xfu,
                                                const float* __restrict__ xhsi) {
    __shared__ float sx[256*32];
    __shared__ float sh[8][32];
    int b = blockIdx.y, blk = blockIdx.x, tid = threadIdx.x;
    size_t base = ((size_t)b*NPIX + (size_t)blk*256) * 32;
    for (int k = 0; k < 32; k++) sx[k*256 + tid] = xfu[base + (size_t)k*256 + tid];
    {
        int c = tid & 31, grp = tid >> 5;
        float s = 0.f;
        for (int p = grp; p < 256; p += 8) s += xhsi[base + (size_t)p*32 + c];
        sh[grp][c] = s;
    }
    __syncthreads();
    int e0 = tid * 4;
    int i = e0 >> 5, j0 = e0 & 31;
    float4 a = make_float4(0.f, 0.f, 0.f, 0.f);
    const float4* sx4 = (const float4*)sx;
    for (int p = 0; p < 256; p++) {
        float xi = sx[p*32 + i];
        float4 xj = sx4[p*8 + (j0 >> 2)];
        a.x += xi * xj.x; a.y += xi * xj.y; a.z += xi * xj.z; a.w += xi * xj.w;
    }
    float* part = &g_part[((size_t)b*256 + blk) * 1056];
    ((float4*)part)[tid] = a;
    if (tid < 32) {
        float t = 0.f;
        for (int g = 0; g < 8; g++) t += sh[g][tid];
        part[1024 + tid] = t;
    }
}

// ---------------- 2) stats stage 2 ----------------
__global__ __launch_bounds__(256) void stats2_k(const float* __restrict__ Wq,
                                                const float* __restrict__ Wk,
                                                const float* __restrict__ fc1,
                                                const float* __restrict__ fc2,
                                                const float* __restrict__ projW,
                                                float* __restrict__ cm_out) {
    int b = blockIdx.x, tid = threadIdx.x;
    __shared__ float scov[1024], savg[32], sQ[1024], sK[1024];
    __shared__ float snq[32], snk[32], sG[256], sA[256], shid[32];
    for (int e = tid; e < 1024; e += 256) {
        float s = 0.f;
        for (int blk = 0; blk < 256; blk++) s += g_part[((size_t)b*256 + blk)*1056 + e];
        scov[e] = s;
    }
    if (tid < 32) {
        float s = 0.f;
        for (int blk = 0; blk < 256; blk++) s += g_part[((size_t)b*256 + blk)*1056 + 1024 + tid];
        savg[tid] = s * (1.f / (float)NPIX);
    }
    __syncthreads();
    for (int e = tid; e < 2048; e += 256) {
        int which = e >> 10; int r = e & 1023; int c = r >> 5, i = r & 31;
        const float* Wm = which ? Wk : Wq;
        float s = 0.f;
        for (int j = 0; j < 32; j++) s += scov[i*32 + j] * Wm[c*32 + j];
        if (which) sK[c*32 + i] = s; else sQ[c*32 + i] = s;
    }
    __syncthreads();
    if (tid < 32) { float s = 0.f; for (int i = 0; i < 32; i++) s += Wq[tid*32+i]*sQ[tid*32+i]; snq[tid] = sqrtf(fmaxf(s, 0.f)); }
    else if (tid < 64) { int c = tid-32; float s = 0.f; for (int i = 0; i < 32; i++) s += Wk[c*32+i]*sK[c*32+i]; snk[c] = sqrtf(fmaxf(s, 0.f)); }
    {
        int h = tid >> 6, d = (tid >> 3) & 7, e = tid & 7;
        int ck = h*8 + d, cq = h*8 + e;
        float s = 0.f;
        for (int i = 0; i < 32; i++) s += Wk[ck*32 + i] * sQ[cq*32 + i];
        sG[tid] = s;
    }
    if (tid >= 64 && tid < 96) {
        int o = tid - 64; float s = 0.f;
        for (int i = 0; i < 32; i++) s += fc1[o*32 + i] * savg[i];
        shid[o] = fmaxf(s, 0.f);
    }
    __syncthreads();
    if (tid < 32) {
        int h = tid >> 3, d = tid & 7;
        float l[8]; float mx = -1e30f;
        float nk = fmaxf(snk[h*8 + d], 1e-12f);
        for (int e = 0; e < 8; e++) {
            float nq = fmaxf(snq[h*8 + e], 1e-12f);
            l[e] = sG[h*64 + d*8 + e] / (nk * nq);
            mx = fmaxf(mx, l[e]);
        }
        float ssum = 0.f;
        for (int e = 0; e < 8; e++) { l[e] = expf(l[e] - mx); ssum += l[e]; }
        float inv = 1.f / ssum;
        for (int e = 0; e < 8; e++) sA[h*64 + d*8 + e] = l[e] * inv;
    } else if (tid >= 128 && tid < 160) {
        int c = tid - 128; float s = 0.f;
        for (int i = 0; i < 32; i++) s += fc2[c*32 + i] * shid[i];
        float m = sigmoidf_(s);
        cm_out[b*32 + c] = m;
        g_cmask[b*32 + c] = m;
    }
    __syncthreads();
    for (int e = tid; e < 1024; e += 256) {
        int o = e >> 5, cp = e & 31, hp = cp >> 3, dp = cp & 7;
        float s = 0.f;
        for (int d = 0; d < 8; d++) s += projW[o*32 + hp*8 + d] * sA[hp*64 + d*8 + dp];
        g_M[b*1024 + e] = s;
    }
}

// ---------------- 3) spatial mask: 16w x 32h tile, 4 px/thread, reg-blocked ----------------
#define SM_TW 16
#define SM_TH 32
#define SM_CW 22
#define SM_CWP 23
#define SM_RH 38
#define SM_STR 36
#define SMASK_XF (SM_RH*SM_CWP*SM_STR)
#define SMASK_SMEM ((SMASK_XF + 49*32) * 4)

__global__ __launch_bounds__(128) void smask_k(const float* __restrict__ xmsi,
                                               float* __restrict__ sm_out) {
    extern __shared__ float dyn[];
    float* sx = dyn;
    float* kc = dyn + SMASK_XF;
    int tid = threadIdx.x, bx = blockIdx.x, by = blockIdx.y, b = blockIdx.z;
    for (int e = tid; e < 49*32; e += 128) kc[e] = g_kcomb[e];
    for (int slot = tid; slot < SM_RH*SM_CW; slot += 128) {
        int r = slot / SM_CW, c = slot % SM_CW;
        int gh = by*SM_TH + r - 3, gw = bx*SM_TW + c - 3;
        float4* dst = (float4*)&sx[(r*SM_CWP + c)*SM_STR];
        if ((unsigned)gh < (unsigned)HH && (unsigned)gw < (unsigned)WW) {
            const float4* src = (const float4*)(xmsi + (((size_t)b*HH + gh)*WW + gw)*32);
            #pragma unroll
            for (int i4 = 0; i4 < 8; i4++) dst[i4] = src[i4];
        } else {
            #pragma unroll
            for (int i4 = 0; i4 < 8; i4++) dst[i4] = make_float4(0.f,0.f,0.f,0.f);
        }
    }
    __syncthreads();
    int ty = tid >> 2;
    int tq = (tid & 3) * 4;
    ull acc[4];
    #pragma unroll
    for (int p = 0; p < 4; p++) acc[p] = 0ull;
    #pragma unroll 1
    for (int cg = 0; cg < 8; cg++) {
        #pragma unroll 1
        for (int dy = 0; dy < 7; dy++) {
            ulonglong2 xw[10];
            #pragma unroll
            for (int j = 0; j < 10; j++)
                xw[j] = *(const ulonglong2*)&sx[((ty+dy)*SM_CWP + tq + j)*SM_STR + cg*4];
            #pragma unroll
            for (int dx = 0; dx < 7; dx++) {
                ulonglong2 wv = *(const ulonglong2*)&kc[(dy*7 + dx)*32 + cg*4];
                #pragma unroll
                for (int p = 0; p < 4; p++) {
                    fma2(acc[p], xw[dx+p].x, wv.x);
                    fma2(acc[p], xw[dx+p].y, wv.y);
                }
            }
        }
    }
    int h = by*SM_TH + ty;
    #pragma unroll
    for (int p = 0; p < 4; p++) {
        int w = bx*SM_TW + tq + p;
        float m = sigmoidf_(hadd2(acc[p]));
        g_smask[(size_t)b*NPIX + (size_t)h*WW + w] = m;
        sm_out[(size_t)b*NPIX + (size_t)w*HH + h] = m;
    }
}

// ---------------- 4) gated V: o-pair (R2 style) ----------------
__global__ __launch_bounds__(256) void vgated_k(const float* __restrict__ xfu,
                                                const float* __restrict__ Wv) {
    __shared__ float ws[32*32];  // ws[i*32+o] = Wv[o*32+i]
    __shared__ float cm[32];
    int tid = threadIdx.x, h = blockIdx.x, b = blockIdx.y;
    for (int e = tid; e < 1024; e += 256) {
        int o = e >> 5, i = e & 31;
        ws[i*32 + o] = Wv[e];
    }
    if (tid < 32) cm[tid] = g_cmask[b*32 + tid];
    __syncthreads();
    size_t pidx = (size_t)b*NPIX + (size_t)h*WW + tid;
    const float4* px = (const float4*)(xfu + pidx*32);
    ull acc[16];
    #pragma unroll
    for (int q = 0; q < 16; q++) acc[q] = 0ull;
    #pragma unroll
    for (int i4 = 0; i4 < 8; i4++) {
        float4 v = px[i4];
        #pragma unroll
        for (int i = 0; i < 4; i++) {
            ull a = pk2((&v.x)[i]);
            const ulonglong2* wr = (const ulonglong2*)&ws[(i4*4 + i)*32];
            #pragma unroll
            for (int q = 0; q < 8; q++) {
                ulonglong2 wv = wr[q];
                fma2(acc[2*q], a, wv.x);
                fma2(acc[2*q+1], a, wv.y);
            }
        }
    }
    float sm = g_smask[pidx];
    float4* ob = (float4*)(g_vg + pidx*32);
    #pragma unroll
    for (int i4 = 0; i4 < 8; i4++) {
        float2 p0 = upk(acc[i4*2]), p1 = upk(acc[i4*2+1]);
        float4 r;
        r.x = p0.x * sm * cm[i4*4];
        r.y = p0.y * sm * cm[i4*4+1];
        r.z = p1.x * sm * cm[i4*4+2];
        r.w = p1.y * sm * cm[i4*4+3];
        ob[i4] = r;
    }
}

// ---------------- 5) 3x3 conv: o-pair, 4 px/thread, x register window ----------------
// mode 0: g_vg -> g_vspec (residual = x_hsi); mode 1: g_vspec -> g_tpos (bias+gelu)
__global__ __launch_bounds__(64) void conv3_k(const float* __restrict__ wsrc,
                                              const float* __restrict__ bias,
                                              const float* __restrict__ resid,
                                              int mode, int do_gelu) {
    __shared__ float ws[9*32*32];  // [tap][i][o], o contiguous
    __shared__ float sb[32];
    int tid = threadIdx.x;
    for (int e = tid; e < 9216; e += 64) {
        int t = e >> 10, i = (e >> 5) & 31, o = e & 31;
        int dh = t / 3, dw = t % 3;
        ws[e] = wsrc[((o*32 + i)*3 + dw)*3 + dh];  // tap-swap for (0,3,2,1) world
    }
    if (tid < 32) sb[tid] = bias ? bias[tid] : 0.f;
    __syncthreads();
    const float* in = (mode == 0) ? g_vg : g_vspec;
    float* outp = (mode == 0) ? g_vspec : g_tpos;
    int h = blockIdx.x, b = blockIdx.y;
    int w0 = tid * 4;
    ull acc[4][16];
    #pragma unroll
    for (int p = 0; p < 4; p++)
        #pragma unroll
        for (int q = 0; q < 16; q++) acc[p][q] = 0ull;
    #pragma unroll 1
    for (int dh = -1; dh <= 1; dh++) {
        int hh = h + dh; if ((unsigned)hh >= (unsigned)HH) continue;
        const float* rowp = in + (((size_t)b*HH + hh)*WW) * 32;
        #pragma unroll 1
        for (int i4 = 0; i4 < 8; i4++) {
            // 6-column x window for this channel-quad
            float4 xc[6];
            #pragma unroll
            for (int c = 0; c < 6; c++) {
                int ww = w0 - 1 + c;
                xc[c] = ((unsigned)ww < (unsigned)WW)
                        ? ((const float4*)(rowp + (size_t)ww*32))[i4]
                        : make_float4(0.f,0.f,0.f,0.f);
            }
            #pragma unroll
            for (int dw = 0; dw < 3; dw++) {
                const float* wt = &ws[((dh+1)*3 + dw)*1024 + i4*4*32];
                #pragma unroll
                for (int i = 0; i < 4; i++) {
                    ulonglong2 wv[8];
                    const ulonglong2* wr = (const ulonglong2*)(wt + i*32);
                    #pragma unroll
                    for (int q = 0; q < 8; q++) wv[q] = wr[q];
                    #pragma unroll
                    for (int p = 0; p < 4; p++) {
                        ull a = pk2((&xc[dw+p].x)[i]);
                        #pragma unroll
                        for (int q = 0; q < 8; q++) {
                            fma2(acc[p][2*q],   a, wv[q].x);
                            fma2(acc[p][2*q+1], a, wv[q].y);
                        }
                    }
                }
            }
        }
    }
    #pragma unroll 1
    for (int p = 0; p < 4; p++) {
        size_t pidx = (((size_t)b*HH + h)*WW + (w0 + p)) * 32;
        float out[32];
        #pragma unroll
        for (int q = 0; q < 16; q++) {
            float2 f = upk(acc[p][q]);
            out[2*q] = f.x + sb[2*q];
            out[2*q+1] = f.y + sb[2*q+1];
        }
        if (resid) {
            const float4* r4 = (const float4*)(resid + pidx);
            #pragma unroll
            for (int i4 = 0; i4 < 8; i4++) {
                float4 rv = r4[i4];
                out[i4*4] += rv.x; out[i4*4+1] += rv.y; out[i4*4+2] += rv.z; out[i4*4+3] += rv.w;
            }
        }
        if (do_gelu) {
            #pragma unroll
            for (int o = 0; o < 32; o++) out[o] = gelu_exact(out[o]);
        }
        float4* ob = (float4*)(outp + pidx);
        #pragma unroll
        for (int i4 = 0; i4 < 8; i4++)
            ob[i4] = make_float4(out[i4*4], out[i4*4+1], out[i4*4+2], out[i4*4+3]);
    }
}

// ---------------- 6) final: o-pair, 2 px/thread ----------------
__global__ __launch_bounds__(128) void final_k(const float* __restrict__ w2src,
                                               const float* __restrict__ b2,
                                               const float* __restrict__ projb) {
    __shared__ float ws[9*32*32];   // [tap][i][o]
    __shared__ float wm[1024];      // wm[c*32+o] = M[o][c]
    __shared__ float sb2[32], spb[32];
    int tid = threadIdx.x, h = blockIdx.x, b = blockIdx.y;
    for (int e = tid; e < 9216; e += 128) {
        int t = e >> 10, i = (e >> 5) & 31, o = e & 31;
        int dh = t / 3, dw = t % 3;
        ws[e] = w2src[((o*32 + i)*3 + dw)*3 + dh];
    }
    for (int e = tid; e < 1024; e += 128) {
        int c = e >> 5, o = e & 31;
        wm[c*32 + o] = g_M[b*1024 + o*32 + c];
    }
    if (tid < 32) { sb2[tid] = b2[tid]; spb[tid] = projb[tid]; }
    __syncthreads();
    int w0 = tid * 2;
    ull acc[2][16];
    #pragma unroll
    for (int p = 0; p < 2; p++)
        #pragma unroll
        for (int q = 0; q < 16; q++) acc[p][q] = 0ull;
    // conv3x3 over g_tpos
    #pragma unroll 1
    for (int dh = -1; dh <= 1; dh++) {
        int hh = h + dh; if ((unsigned)hh >= (unsigned)HH) continue;
        const float* rowp = g_tpos + (((size_t)b*HH + hh)*WW) * 32;
        #pragma unroll 1
        for (int i4 = 0; i4 < 8; i4++) {
            float4 xc[4];
            #pragma unroll
            for (int c = 0; c < 4; c++) {
                int ww = w0 - 1 + c;
                xc[c] = ((unsigned)ww < (unsigned)WW)
                        ? ((const float4*)(rowp + (size_t)ww*32))[i4]
                        : make_float4(0.f,0.f,0.f,0.f);
            }
            #pragma unroll
            for (int dw = 0; dw < 3; dw++) {
                const float* wt = &ws[((dh+1)*3 + dw)*1024 + i4*4*32];
                #pragma unroll
                for (int i = 0; i < 4; i++) {
                    ulonglong2 wv[8];
                    const ulonglong2* wr = (const ulonglong2*)(wt + i*32);
                    #pragma unroll
                    for (int q = 0; q < 8; q++) wv[q] = wr[q];
                    #pragma unroll
                    for (int p = 0; p < 2; p++) {
                        ull a = pk2((&xc[dw+p].x)[i]);
                        #pragma unroll
                        for (int q = 0; q < 8; q++) {
                            fma2(acc[p][2*q],   a, wv[q].x);
                            fma2(acc[p][2*q+1], a, wv[q].y);
                        }
                    }
                }
            }
        }
    }
    // per-pixel matvec + combine + store
    #pragma unroll 1
    for (int p = 0; p < 2; p++) {
        size_t pidx = (((size_t)b*HH + h)*WW + (w0 + p)) * 32;
        ull tmp[16];
        #pragma unroll
        for (int q = 0; q < 16; q++) tmp[q] = 0ull;
        const float4* pv = (const float4*)(g_vspec + pidx);
        #pragma unroll
        for (int i4 = 0; i4 < 8; i4++) {
            float4 v = pv[i4];
            #pragma unroll
            for (int i = 0; i < 4; i++) {
                ull a = pk2((&v.x)[i]);
                const ulonglong2* wr = (const ulonglong2*)&wm[(i4*4 + i)*32];
                #pragma unroll
                for (int q = 0; q < 8; q++) {
                    ulonglong2 wv = wr[q];
                    fma2(tmp[2*q],   a, wv.x);
                    fma2(tmp[2*q+1], a, wv.y);
                }
            }
        }
        float4* ob = (float4*)(g_outn + pidx);
        #pragma unroll
        for (int i4 = 0; i4 < 8; i4++) {
            float2 m0 = upk(tmp[i4*2]), m1 = upk(tmp[i4*2+1]);
            float2 c0 = upk(acc[p][i4*2]), c1 = upk(acc[p][i4*2+1]);
            float4 r;
            r.x = gelu_exact(m0.x + spb[i4*4])   + sb2[i4*4]   + c0.x;
            r.y = gelu_exact(m0.y + spb[i4*4+1]) + sb2[i4*4+1] + c0.y;
            r.z = gelu_exact(m1.x + spb[i4*4+2]) + sb2[i4*4+2] + c1.x;
            r.w = gelu_exact(m1.y + spb[i4*4+3]) + sb2[i4*4+3] + c1.y;
            ob[i4] = r;
        }
    }
}

// ---------------- 7) transpose NHWC -> (b,c,w,h) ----------------
__global__ void transpose_k(float* __restrict__ out0) {
    __shared__ float tile[32][33];
    int b = blockIdx.z, w = blockIdx.y, h0 = blockIdx.x * 32;
    int tx = threadIdx.x, ty = threadIdx.y;
    tile[ty][tx] = g_outn[(((size_t)b*HH + (h0 + ty))*WW + w)*32 + tx];
    __syncthreads();
    out0[(((size_t)b*CC + ty)*WW + w)*HH + h0 + tx] = tile[tx][ty];
}

// ---------------- launch ----------------
extern "C" void kernel_launch(void* const* d_in, const int* in_sizes, int n_in,
                              void* d_out, int out_size) {
    const float* x_fu   = (const float*)d_in[0];
    const float* x_msi  = (const float*)d_in[1];
    const float* x_hsi  = (const float*)d_in[2];
    const float* Wq     = (const float*)d_in[3];
    const float* Wk     = (const float*)d_in[4];
    const float* Wv     = (const float*)d_in[5];
    const float* proj_W = (const float*)d_in[6];
    const float* proj_b = (const float*)d_in[7];
    const float* pos1_W = (const float*)d_in[8];
    const float* pos1_b = (const float*)d_in[9];
    const float* pos2_W = (const float*)d_in[10];
    const float* pos2_b = (const float*)d_in[11];
    const float* ca_fc1 = (const float*)d_in[12];
    const float* ca_fc2 = (const float*)d_in[13];
    const float* sa_c1a = (const float*)d_in[14];
    const float* sa_c1b = (const float*)d_in[15];
    const float* sa_c2a = (const float*)d_in[16];
    const float* sa_c2b = (const float*)d_in[17];
    const float* sa_c3  = (const float*)d_in[18];
    const float* attn_W = (const float*)d_in[19];

    float* out0   = (float*)d_out;
    float* cm_out = out0 + IMG_ELEMS;
    float* sm_out = cm_out + BB*CC;

    cudaFuncSetAttribute(smask_k, cudaFuncAttributeMaxDynamicSharedMemorySize, SMASK_SMEM);

    dim3 g(HH, BB);
    prep_k  <<<1, 256>>>(sa_c1a, sa_c1b, sa_c2a, sa_c2b, sa_c3);
    stats1_k<<<dim3(256, BB), 256>>>(x_fu, x_hsi);
    stats2_k<<<BB, 256>>>(Wq, Wk, ca_fc1, ca_fc2, proj_W, cm_out);
    smask_k <<<dim3(WW/SM_TW, HH/SM_TH, BB), 128, SMASK_SMEM>>>(x_msi, sm_out);
    vgated_k<<<g, 256>>>(x_fu, Wv);
    conv3_k <<<g, 64>>>(attn_W, (const float*)nullptr, x_hsi, 0, 0);   // v_spec
    conv3_k <<<g, 64>>>(pos1_W, pos1_b, (const float*)nullptr, 1, 1);  // t_pos
    final_k <<<g, 128>>>(pos2_W, pos2_b, proj_b);
    transpose_k<<<dim3(HH/32, WW, BB), dim3(32, 32)>>>(out0);
}

// round 6
// speedup vs baseline: 1.2271x; 1.2271x over previous
#include <cuda_runtime.h>
#include <math.h>

// ---------------- problem constants ----------------
#define BB 4
#define HH 256
#define WW 256
#define CC 32
#define NPIX (HH*WW)            // 65536
#define IMG_ELEMS (BB*NPIX*CC)  // 8388608

typedef unsigned long long ull;

// ---------------- device scratch ----------------
__device__ float g_part[BB*256*1056];
__device__ float g_M[BB*1024];
__device__ float g_cmask[BB*CC];
__device__ float g_smask[BB*NPIX];
__device__ float g_kcomb[49*32];
__device__ float g_vg[IMG_ELEMS];
__device__ float g_vspec[IMG_ELEMS];
__device__ float g_tpos[IMG_ELEMS];
__device__ float g_outn[IMG_ELEMS];

__device__ __forceinline__ float gelu_exact(float x) {
    return 0.5f * x * (1.0f + erff(x * 0.70710678118654752f));
}
__device__ __forceinline__ float sigmoidf_(float x) {
    return 1.0f / (1.0f + expf(-x));
}

// ---------------- packed f32x2 helpers ----------------
__device__ __forceinline__ void fma2(ull& c, ull a, ull b) {
    asm("fma.rn.f32x2 %0, %1, %2, %0;" : "+l"(c) : "l"(a), "l"(b));
}
__device__ __forceinline__ ull pk2(float x) {          // {x, x}
    ull r; asm("mov.b64 %0, {%1, %1};" : "=l"(r) : "f"(x)); return r;
}
__device__ __forceinline__ ull pkpair(float lo, float hi) {
    ull r; asm("mov.b64 %0, {%1, %2};" : "=l"(r) : "f"(lo), "f"(hi)); return r;
}
__device__ __forceinline__ float2 upk(ull v) {
    float2 f; asm("mov.b64 {%0, %1}, %2;" : "=f"(f.x), "=f"(f.y) : "l"(v)); return f;
}
__device__ __forceinline__ float hadd2(ull v) {
    float2 f = upk(v); return f.x + f.y;
}

// ---------------- 0) fold spatial-attention kernels ----------------
__global__ void prep_k(const float* __restrict__ c1a, const float* __restrict__ c1b,
                       const float* __restrict__ c2a, const float* __restrict__ c2b,
                       const float* __restrict__ c3) {
    int tid = threadIdx.x;
    float w3 = c3[0], w7 = c3[1];
    for (int e = tid; e < 49*32; e += 256) {
        int t = e >> 5, i = e & 31;
        int ty = t / 7 - 3, tx = t % 7 - 3;
        float s = 0.f;
        for (int o = 0; o < 32; o++)
            s += c2b[o] * c2a[((o*32 + i)*7 + (tx+3))*7 + (ty+3)];
        s *= w7;
        if (tx >= -1 && tx <= 1 && ty >= -1 && ty <= 1) {
            float s1 = 0.f;
            for (int o = 0; o < 32; o++)
                s1 += c1b[o] * c1a[((o*32 + i)*3 + (tx+1))*3 + (ty+1)];
            s += w3 * s1;
        }
        g_kcomb[e] = s;
    }
}

// ---------------- 1) stats stage 1 ----------------
__global__ __launch_bounds__(256) void stats1_k(const float* __restrict__ xfu,
                                                const float* __restrict__ xhsi) {
    __shared__ float sx[256*32];
    __shared__ float sh[8][32];
    int b = blockIdx.y, blk = blockIdx.x, tid = threadIdx.x;
    size_t base = ((size_t)b*NPIX + (size_t)blk*256) * 32;
    for (int k = 0; k < 32; k++) sx[k*256 + tid] = xfu[base + (size_t)k*256 + tid];
    {
        int c = tid & 31, grp = tid >> 5;
        float s = 0.f;
        for (int p = grp; p < 256; p += 8) s += xhsi[base + (size_t)p*32 + c];
        sh[grp][c] = s;
    }
    __syncthreads();
    int e0 = tid * 4;
    int i = e0 >> 5, j0 = e0 & 31;
    float4 a = make_float4(0.f, 0.f, 0.f, 0.f);
    const float4* sx4 = (const float4*)sx;
    for (int p = 0; p < 256; p++) {
        float xi = sx[p*32 + i];
        float4 xj = sx4[p*8 + (j0 >> 2)];
        a.x += xi * xj.x; a.y += xi * xj.y; a.z += xi * xj.z; a.w += xi * xj.w;
    }
    float* part = &g_part[((size_t)b*256 + blk) * 1056];
    ((float4*)part)[tid] = a;
    if (tid < 32) {
        float t = 0.f;
        for (int g = 0; g < 8; g++) t += sh[g][tid];
        part[1024 + tid] = t;
    }
}

// ---------------- 2) stats stage 2 ----------------
__global__ __launch_bounds__(256) void stats2_k(const float* __restrict__ Wq,
                                                const float* __restrict__ Wk,
                                                const float* __restrict__ fc1,
                                                const float* __restrict__ fc2,
                                                const float* __restrict__ projW,
                                                float* __restrict__ cm_out) {
    int b = blockIdx.x, tid = threadIdx.x;
    __shared__ float scov[1024], savg[32], sQ[1024], sK[1024];
    __shared__ float snq[32], snk[32], sG[256], sA[256], shid[32];
    for (int e = tid; e < 1024; e += 256) {
        float s = 0.f;
        for (int blk = 0; blk < 256; blk++) s += g_part[((size_t)b*256 + blk)*1056 + e];
        scov[e] = s;
    }
    if (tid < 32) {
        float s = 0.f;
        for (int blk = 0; blk < 256; blk++) s += g_part[((size_t)b*256 + blk)*1056 + 1024 + tid];
        savg[tid] = s * (1.f / (float)NPIX);
    }
    __syncthreads();
    for (int e = tid; e < 2048; e += 256) {
        int which = e >> 10; int r = e & 1023; int c = r >> 5, i = r & 31;
        const float* Wm = which ? Wk : Wq;
        float s = 0.f;
        for (int j = 0; j < 32; j++) s += scov[i*32 + j] * Wm[c*32 + j];
        if (which) sK[c*32 + i] = s; else sQ[c*32 + i] = s;
    }
    __syncthreads();
    if (tid < 32) { float s = 0.f; for (int i = 0; i < 32; i++) s += Wq[tid*32+i]*sQ[tid*32+i]; snq[tid] = sqrtf(fmaxf(s, 0.f)); }
    else if (tid < 64) { int c = tid-32; float s = 0.f; for (int i = 0; i < 32; i++) s += Wk[c*32+i]*sK[c*32+i]; snk[c] = sqrtf(fmaxf(s, 0.f)); }
    {
        int h = tid >> 6, d = (tid >> 3) & 7, e = tid & 7;
        int ck = h*8 + d, cq = h*8 + e;
        float s = 0.f;
        for (int i = 0; i < 32; i++) s += Wk[ck*32 + i] * sQ[cq*32 + i];
        sG[tid] = s;
    }
    if (tid >= 64 && tid < 96) {
        int o = tid - 64; float s = 0.f;
        for (int i = 0; i < 32; i++) s += fc1[o*32 + i] * savg[i];
        shid[o] = fmaxf(s, 0.f);
    }
    __syncthreads();
    if (tid < 32) {
        int h = tid >> 3, d = tid & 7;
        float l[8]; float mx = -1e30f;
        float nk = fmaxf(snk[h*8 + d], 1e-12f);
        for (int e = 0; e < 8; e++) {
            float nq = fmaxf(snq[h*8 + e], 1e-12f);
            l[e] = sG[h*64 + d*8 + e] / (nk * nq);
            mx = fmaxf(mx, l[e]);
        }
        float ssum = 0.f;
        for (int e = 0; e < 8; e++) { l[e] = expf(l[e] - mx); ssum += l[e]; }
        float inv = 1.f / ssum;
        for (int e = 0; e < 8; e++) sA[h*64 + d*8 + e] = l[e] * inv;
    } else if (tid >= 128 && tid < 160) {
        int c = tid - 128; float s = 0.f;
        for (int i = 0; i < 32; i++) s += fc2[c*32 + i] * shid[i];
        float m = sigmoidf_(s);
        cm_out[b*32 + c] = m;
        g_cmask[b*32 + c] = m;
    }
    __syncthreads();
    for (int e = tid; e < 1024; e += 256) {
        int o = e >> 5, cp = e & 31, hp = cp >> 3, dp = cp & 7;
        float s = 0.f;
        for (int d = 0; d < 8; d++) s += projW[o*32 + hp*8 + d] * sA[hp*64 + d*8 + dp];
        g_M[b*1024 + e] = s;
    }
}

// ---------------- 3) spatial mask: 16x16 tile, 1 px/thread, 71KB smem ----------------
#define SM_T   16
#define SM_RH  22             // halo rows
#define SM_CWP 23             // padded row stride in pixels (odd 16B-unit stride)
#define SM_STR 36             // per-pixel channel stride (floats) = 9 x 16B units (odd)
#define SMASK_XF (SM_RH*SM_CWP*SM_STR)
#define SMASK_SMEM (SMASK_XF * 4)

__global__ __launch_bounds__(256) void smask_k(const float* __restrict__ xmsi,
                                               float* __restrict__ sm_out) {
    extern __shared__ float sx[];
    int tid = threadIdx.x, bx = blockIdx.x, by = blockIdx.y, b = blockIdx.z;
    for (int slot = tid; slot < SM_RH*22; slot += 256) {
        int r = slot / 22, c = slot % 22;
        int gh = by*SM_T + r - 3, gw = bx*SM_T + c - 3;
        float4* dst = (float4*)&sx[(r*SM_CWP + c)*SM_STR];
        if ((unsigned)gh < (unsigned)HH && (unsigned)gw < (unsigned)WW) {
            const float4* src = (const float4*)(xmsi + (((size_t)b*HH + gh)*WW + gw)*32);
            #pragma unroll
            for (int i4 = 0; i4 < 8; i4++) dst[i4] = src[i4];
        } else {
            #pragma unroll
            for (int i4 = 0; i4 < 8; i4++) dst[i4] = make_float4(0.f,0.f,0.f,0.f);
        }
    }
    __syncthreads();
    int ty = tid >> 4, tx = tid & 15;
    ull acc = 0ull;
    #pragma unroll 1
    for (int cg = 0; cg < 8; cg++) {
        #pragma unroll 1
        for (int dy = 0; dy < 7; dy++) {
            ulonglong2 xw[7];
            #pragma unroll
            for (int j = 0; j < 7; j++)
                xw[j] = *(const ulonglong2*)&sx[((ty+dy)*SM_CWP + tx + j)*SM_STR + cg*4];
            #pragma unroll
            for (int dx = 0; dx < 7; dx++) {
                ulonglong2 kv = *(const ulonglong2*)&g_kcomb[(dy*7 + dx)*32 + cg*4];
                fma2(acc, xw[dx].x, kv.x);
                fma2(acc, xw[dx].y, kv.y);
            }
        }
    }
    float m = sigmoidf_(hadd2(acc));
    int h = by*SM_T + ty, w = bx*SM_T + tx;
    g_smask[(size_t)b*NPIX + (size_t)h*WW + w] = m;
    sm_out[(size_t)b*NPIX + (size_t)w*HH + h] = m;
}

// ---------------- 4) gated V: o-pair ----------------
__global__ __launch_bounds__(256) void vgated_k(const float* __restrict__ xfu,
                                                const float* __restrict__ Wv) {
    __shared__ float ws[32*32];  // ws[i*32+o] = Wv[o*32+i]
    __shared__ float cm[32];
    int tid = threadIdx.x, h = blockIdx.x, b = blockIdx.y;
    for (int e = tid; e < 1024; e += 256) {
        int o = e >> 5, i = e & 31;
        ws[i*32 + o] = Wv[e];
    }
    if (tid < 32) cm[tid] = g_cmask[b*32 + tid];
    __syncthreads();
    size_t pidx = (size_t)b*NPIX + (size_t)h*WW + tid;
    const float4* px = (const float4*)(xfu + pidx*32);
    ull acc[16];
    #pragma unroll
    for (int q = 0; q < 16; q++) acc[q] = 0ull;
    #pragma unroll
    for (int i4 = 0; i4 < 8; i4++) {
        float4 v = px[i4];
        #pragma unroll
        for (int i = 0; i < 4; i++) {
            ull a = pk2((&v.x)[i]);
            const ulonglong2* wr = (const ulonglong2*)&ws[(i4*4 + i)*32];
            #pragma unroll
            for (int q = 0; q < 8; q++) {
                ulonglong2 wv = wr[q];
                fma2(acc[2*q], a, wv.x);
                fma2(acc[2*q+1], a, wv.y);
            }
        }
    }
    float sm = g_smask[pidx];
    float4* ob = (float4*)(g_vg + pidx*32);
    #pragma unroll
    for (int i4 = 0; i4 < 8; i4++) {
        float2 p0 = upk(acc[i4*2]), p1 = upk(acc[i4*2+1]);
        float4 r;
        r.x = p0.x * sm * cm[i4*4];
        r.y = p0.y * sm * cm[i4*4+1];
        r.z = p1.x * sm * cm[i4*4+2];
        r.w = p1.y * sm * cm[i4*4+3];
        ob[i4] = r;
    }
}

// ---------------- conv epilogue (constant-indexed after inlining) ----------------
__device__ __forceinline__ void conv_epi(ull (&acc)[16], float* __restrict__ outp,
                                         const float* __restrict__ resid,
                                         size_t pidx, int do_gelu) {
    float out[32];
    #pragma unroll
    for (int q = 0; q < 16; q++) {
        float2 f = upk(acc[q]);
        out[2*q] = f.x; out[2*q+1] = f.y;
    }
    if (resid) {
        const float4* r4 = (const float4*)(resid + pidx);
        #pragma unroll
        for (int i4 = 0; i4 < 8; i4++) {
            float4 rv = r4[i4];
            out[i4*4] += rv.x; out[i4*4+1] += rv.y; out[i4*4+2] += rv.z; out[i4*4+3] += rv.w;
        }
    }
    if (do_gelu) {
        #pragma unroll
        for (int o = 0; o < 32; o++) out[o] = gelu_exact(out[o]);
    }
    float4* ob = (float4*)(outp + pidx);
    #pragma unroll
    for (int i4 = 0; i4 < 8; i4++)
        ob[i4] = make_float4(out[i4*4], out[i4*4+1], out[i4*4+2], out[i4*4+3]);
}

// ---------------- 5) 3x3 conv: o-pair, 2 px/thread, no dynamic reg indexing ----------------
__global__ __launch_bounds__(128) void conv3_k(const float* __restrict__ wsrc,
                                               const float* __restrict__ bias,
                                               const float* __restrict__ resid,
                                               int mode, int do_gelu) {
    __shared__ float ws[9*32*32];  // [tap][i][o], o contiguous
    __shared__ float sb[32];
    int tid = threadIdx.x;
    for (int e = tid; e < 9216; e += 128) {
        int o = e & 31, i = (e >> 5) & 31, t = e >> 10;
        int dh = t / 3, dw = t % 3;
        ws[e] = wsrc[((o*32 + i)*3 + dw)*3 + dh];  // tap-swap for (0,3,2,1) world
    }
    if (tid < 32) sb[tid] = bias ? bias[tid] : 0.f;
    __syncthreads();
    const float* in = (mode == 0) ? g_vg : g_vspec;
    float* outp = (mode == 0) ? g_vspec : g_tpos;
    int h = blockIdx.x, b = blockIdx.y, w0 = tid * 2;
    ull acc0[16], acc1[16];
    #pragma unroll
    for (int q = 0; q < 16; q++) {
        ull bv = pkpair(sb[2*q], sb[2*q+1]);
        acc0[q] = bv; acc1[q] = bv;
    }
    #pragma unroll 1
    for (int dh = -1; dh <= 1; dh++) {
        int hh = h + dh; if ((unsigned)hh >= (unsigned)HH) continue;
        #pragma unroll 1
        for (int dw = -1; dw <= 1; dw++) {
            int ww0 = w0 + dw, ww1 = w0 + 1 + dw;
            bool v0 = (unsigned)ww0 < (unsigned)WW, v1 = (unsigned)ww1 < (unsigned)WW;
            const float4* p0 = (const float4*)(in + (((size_t)b*HH + hh)*WW + ww0)*32);
            const float4* p1 = (const float4*)(in + (((size_t)b*HH + hh)*WW + ww1)*32);
            const float* wt = &ws[((dh+1)*3 + (dw+1)) * 1024];
            #pragma unroll
            for (int i4 = 0; i4 < 8; i4++) {
                float4 x0 = v0 ? p0[i4] : make_float4(0.f,0.f,0.f,0.f);
                float4 x1 = v1 ? p1[i4] : make_float4(0.f,0.f,0.f,0.f);
                #pragma unroll
                for (int i = 0; i < 4; i++) {
                    ull a0 = pk2((&x0.x)[i]);
                    ull a1 = pk2((&x1.x)[i]);
                    const ulonglong2* wr = (const ulonglong2*)(wt + (i4*4 + i)*32);
                    #pragma unroll
                    for (int q = 0; q < 8; q++) {
                        ulonglong2 wv = wr[q];
                        fma2(acc0[2*q],   a0, wv.x);
                        fma2(acc0[2*q+1], a0, wv.y);
                        fma2(acc1[2*q],   a1, wv.x);
                        fma2(acc1[2*q+1], a1, wv.y);
                    }
                }
            }
        }
    }
    size_t pidx0 = (((size_t)b*HH + h)*WW + w0) * 32;
    conv_epi(acc0, outp, resid, pidx0, do_gelu);
    conv_epi(acc1, outp, resid, pidx0 + 32, do_gelu);
}

// ---------------- 6) final: o-pair, 1 px/thread ----------------
__global__ __launch_bounds__(256) void final_k(const float* __restrict__ w2src,
                                               const float* __restrict__ b2,
                                               const float* __restrict__ projb) {
    __shared__ float ws[9*32*32];
    __shared__ float wm[1024];   // wm[c*32+o] = M[o][c]
    __shared__ float sb2[32], spb[32];
    int tid = threadIdx.x, h = blockIdx.x, b = blockIdx.y;
    for (int e = tid; e < 9216; e += 256) {
        int o = e & 31, i = (e >> 5) & 31, t = e >> 10;
        int dh = t / 3, dw = t % 3;
        ws[e] = w2src[((o*32 + i)*3 + dw)*3 + dh];
    }
    for (int e = tid; e < 1024; e += 256) {
        int c = e >> 5, o = e & 31;
        wm[c*32 + o] = g_M[b*1024 + o*32 + c];
    }
    if (tid < 32) { sb2[tid] = b2[tid]; spb[tid] = projb[tid]; }
    __syncthreads();
    int w = tid;
    size_t pidx = (((size_t)b*HH + h)*WW + w) * 32;
    ull acc[16];
    #pragma unroll
    for (int q = 0; q < 16; q++) acc[q] = pkpair(spb[2*q], spb[2*q+1]);
    // matvec M @ v_spec
    {
        const float4* pv = (const float4*)(g_vspec + pidx);
        #pragma unroll
        for (int i4 = 0; i4 < 8; i4++) {
            float4 v = pv[i4];
            #pragma unroll
            for (int i = 0; i < 4; i++) {
                ull a = pk2((&v.x)[i]);
                const ulonglong2* wr = (const ulonglong2*)&wm[(i4*4 + i)*32];
                #pragma unroll
                for (int q = 0; q < 8; q++) {
                    ulonglong2 wv = wr[q];
                    fma2(acc[2*q],   a, wv.x);
                    fma2(acc[2*q+1], a, wv.y);
                }
            }
        }
    }
    #pragma unroll
    for (int q = 0; q < 16; q++) {
        float2 f = upk(acc[q]);
        acc[q] = pkpair(gelu_exact(f.x) + sb2[2*q], gelu_exact(f.y) + sb2[2*q+1]);
    }
    // conv3x3 on g_tpos accumulated into acc
    #pragma unroll 1
    for (int dh = -1; dh <= 1; dh++) {
        int hh = h + dh; if ((unsigned)hh >= (unsigned)HH) continue;
        #pragma unroll 1
        for (int dw = -1; dw <= 1; dw++) {
            int ww = w + dw; if ((unsigned)ww >= (unsigned)WW) continue;
            const float4* px = (const float4*)(g_tpos + (((size_t)b*HH + hh)*WW + ww)*32);
            const float* wt = &ws[((dh+1)*3 + (dw+1)) * 1024];
            #pragma unroll
            for (int i4 = 0; i4 < 8; i4++) {
                float4 xv = px[i4];
                #pragma unroll
                for (int i = 0; i < 4; i++) {
                    ull a = pk2((&xv.x)[i]);
                    const ulonglong2* wr = (const ulonglong2*)(wt + (i4*4 + i)*32);
                    #pragma unroll
                    for (int q = 0; q < 8; q++) {
                        ulonglong2 wv = wr[q];
                        fma2(acc[2*q],   a, wv.x);
                        fma2(acc[2*q+1], a, wv.y);
                    }
                }
            }
        }
    }
    float4* ob = (float4*)(g_outn + pidx);
    #pragma unroll
    for (int q = 0; q < 8; q++) {
        float2 f0 = upk(acc[2*q]), f1 = upk(acc[2*q+1]);
        ob[q] = make_float4(f0.x, f0.y, f1.x, f1.y);
    }
}

// ---------------- 7) transpose NHWC -> (b,c,w,h) ----------------
__global__ void transpose_k(float* __restrict__ out0) {
    __shared__ float tile[32][33];
    int b = blockIdx.z, w = blockIdx.y, h0 = blockIdx.x * 32;
    int tx = threadIdx.x, ty = threadIdx.y;
    tile[ty][tx] = g_outn[(((size_t)b*HH + (h0 + ty))*WW + w)*32 + tx];
    __syncthreads();
    out0[(((size_t)b*CC + ty)*WW + w)*HH + h0 + tx] = tile[tx][ty];
}

// ---------------- launch ----------------
extern "C" void kernel_launch(void* const* d_in, const int* in_sizes, int n_in,
                              void* d_out, int out_size) {
    const float* x_fu   = (const float*)d_in[0];
    const float* x_msi  = (const float*)d_in[1];
    const float* x_hsi  = (const float*)d_in[2];
    const float* Wq     = (const float*)d_in[3];
    const float* Wk     = (const float*)d_in[4];
    const float* Wv     = (const float*)d_in[5];
    const float* proj_W = (const float*)d_in[6];
    const float* proj_b = (const float*)d_in[7];
    const float* pos1_W = (const float*)d_in[8];
    const float* pos1_b = (const float*)d_in[9];
    const float* pos2_W = (const float*)d_in[10];
    const float* pos2_b = (const float*)d_in[11];
    const float* ca_fc1 = (const float*)d_in[12];
    const float* ca_fc2 = (const float*)d_in[13];
    const float* sa_c1a = (const float*)d_in[14];
    const float* sa_c1b = (const float*)d_in[15];
    const float* sa_c2a = (const float*)d_in[16];
    const float* sa_c2b = (const float*)d_in[17];
    const float* sa_c3  = (const float*)d_in[18];
    const float* attn_W = (const float*)d_in[19];

    float* out0   = (float*)d_out;
    float* cm_out = out0 + IMG_ELEMS;
    float* sm_out = cm_out + BB*CC;

    cudaFuncSetAttribute(smask_k, cudaFuncAttributeMaxDynamicSharedMemorySize, SMASK_SMEM);

    dim3 g(HH, BB);
    prep_k  <<<1, 256>>>(sa_c1a, sa_c1b, sa_c2a, sa_c2b, sa_c3);
    stats1_k<<<dim3(256, BB), 256>>>(x_fu, x_hsi);
    stats2_k<<<BB, 256>>>(Wq, Wk, ca_fc1, ca_fc2, proj_W, cm_out);
    smask_k <<<dim3(WW/SM_T, HH/SM_T, BB), 256, SMASK_SMEM>>>(x_msi, sm_out);
    vgated_k<<<g, 256>>>(x_fu, Wv);
    conv3_k <<<g, 128>>>(attn_W, (const float*)nullptr, x_hsi, 0, 0);   // v_spec
    conv3_k <<<g, 128>>>(pos1_W, pos1_b, (const float*)nullptr, 1, 1);  // t_pos
    final_k <<<g, 256>>>(pos2_W, pos2_b, proj_b);
    transpose_k<<<dim3(HH/32, WW, BB), dim3(32, 32)>>>(out0);
}